// round 3
// baseline (speedup 1.0000x reference)
#include <cuda_runtime.h>

// ---------------- problem constants ----------------
#define B_      8
#define IN_C    32
#define OUT_C   64
#define H_      64
#define W_      64
#define QDIM    36
#define PDIM    8
#define KB      8
#define NPIX    (B_*H_*W_)          // 32768
#define NQP     (QDIM/2)            // 18 q-pairs

#define HP      66
#define CHW     (HP*HP)             // 4356
#define PAD_TOTAL (B_*IN_C*CHW)

#define MRR_A   0.987
#define MRR_R   0.99

typedef unsigned long long u64;

__device__ float g_xpad[PAD_TOTAL];

// ---------------- kernel 1: zero-padded x^2 ----------------
__global__ void prepad_kernel(const float* __restrict__ x) {
    int idx = blockIdx.x * blockDim.x + threadIdx.x;
    if (idx >= PAD_TOTAL) return;
    int wp = idx % HP;
    int t  = idx / HP;
    int hp = t % HP;
    int bc = t / HP;
    float v = 0.0f;
    if (hp >= 1 && hp <= H_ && wp >= 1 && wp <= W_) {
        float xv = x[(bc * H_ + (hp - 1)) * W_ + (wp - 1)];
        v = xv * xv;
    }
    g_xpad[idx] = v;
}

// ---------------- packed f32x2 helpers ----------------
__device__ __forceinline__ u64 pack2(float a, float b) {
    u64 r;
    asm("mov.b64 %0, {%1, %2};" : "=l"(r) : "f"(a), "f"(b));
    return r;
}
__device__ __forceinline__ void unpack2(u64 v, float& a, float& b) {
    asm("mov.b64 {%0, %1}, %2;" : "=f"(a), "=f"(b) : "l"(v));
}
__device__ __forceinline__ u64 mul2(u64 a, u64 b) {
    u64 r;
    asm("mul.rn.f32x2 %0, %1, %2;" : "=l"(r) : "l"(a), "l"(b));
    return r;
}
__device__ __forceinline__ u64 fma2(u64 a, u64 b, u64 c) {
    u64 r;
    asm("fma.rn.f32x2 %0, %1, %2, %3;" : "=l"(r) : "l"(a), "l"(b), "l"(c));
    return r;
}

// ---------------- kernel 2: main compute ----------------
// grid 2048, block 128 (4 warps). warp -> one p value; lane -> pixel.
// thread: 1 pixel x 1 p x 8 t, q in packed pairs. 8 accumulators.
__global__ __launch_bounds__(128, 9) void morr_kernel(const float* __restrict__ wgt,
                                                      const float* __restrict__ mos,
                                                      float* __restrict__ out) {
    // weights prepacked across the q-pair: wpk[qp][p][i] = { |w[2qp,p,i]|, |w[2qp+1,p,i]| }
    __shared__ float2 wpk[NQP * PDIM * KB];   // 9216 B
    __shared__ int    poff[QDIM * KB];        // unfold offsets
    __shared__ float  scl[QDIM];              // -D * rail-scale[q]

    const int tid = threadIdx.x;

    for (int d = tid; d < NQP * PDIM * KB; d += 128) {
        int qp = d >> 6;
        int p  = (d >> 3) & 7;
        int i  = d & 7;
        float w0 = fabsf(wgt[p * (QDIM * KB) + (2 * qp)     * KB + i]);
        float w1 = fabsf(wgt[p * (QDIM * KB) + (2 * qp + 1) * KB + i]);
        wpk[d] = make_float2(w0, w1);
    }
    for (int i = tid; i < QDIM * KB; i += 128) {
        int c = i / 9, r = i % 9;
        poff[i] = c * CHW + (r / 3) * HP + (r % 3);
    }
    if (tid < QDIM) {
        const float D = (float)((1.0 - MRR_A * MRR_A) * (1.0 - MRR_R * MRR_R));
        float sv = (tid < QDIM / 2) ? mos[tid] : -mos[tid - QDIM / 2];
        scl[tid] = -D * sv;
    }
    __syncthreads();

    const int wid  = tid >> 5;
    const int lane = tid & 31;
    const int p    = ((int)blockIdx.x & 1) * 4 + wid;       // 0..7
    const int n    = ((int)blockIdx.x >> 1) * 32 + lane;    // pixel
    const int b = n >> 12;
    const int h = (n >> 6) & 63;
    const int w = n & 63;

    const float* __restrict__ xb = g_xpad + b * (IN_C * CHW) + h * HP + w;

    float acc[8];
#pragma unroll
    for (int t = 0; t < 8; ++t) acc[t] = 0.0f;

    const float C2   = (float)(1.0 + (MRR_A * MRR_R) * (MRR_A * MRR_R));
    const float N2AR = (float)(-2.0 * MRR_A * MRR_R);

    for (int qp = 0; qp < NQP; ++qp) {
        const float a0 = scl[2 * qp];
        const float a1 = scl[2 * qp + 1];

        // gather both q's inputs, pack across the pair
        u64 xsp[8];
#pragma unroll
        for (int s = 0; s < 8; ++s) {
            float x0 = xb[poff[qp * 16 + s]];
            float x1 = xb[poff[qp * 16 + 8 + s]];
            xsp[s] = pack2(x0, x1);
        }

        const u64* __restrict__ wq =
            reinterpret_cast<const u64*>(wpk + (qp * PDIM + p) * KB);
        u64 wr[8];
#pragma unroll
        for (int i = 0; i < 8; ++i) wr[i] = wq[i];   // LDS.64, prepacked

#pragma unroll
        for (int t = 0; t < 8; ++t) {
            // packed circular conv: {phase_q0[t], phase_q1[t]}
            u64 ph = mul2(xsp[0], wr[t]);
#pragma unroll
            for (int s = 1; s < 8; ++s) ph = fma2(xsp[s], wr[(t - s) & 7], ph);

            float ph0, ph1;
            unpack2(ph, ph0, ph1);
            float c0 = __cosf(ph0);
            float c1 = __cosf(ph1);
            float e0 = fmaf(c0, N2AR, C2);
            float e1 = fmaf(c1, N2AR, C2);
            // a0/e0 + a1/e1 = (a0*e1 + a1*e0) / (e0*e1): one RCP per q-pair
            float num = fmaf(a1, e0, a0 * e1);
            float den = e0 * e1;
            float r;
            asm("rcp.approx.f32 %0, %1;" : "=f"(r) : "f"(den));
            acc[t] = fmaf(num, r, acc[t]);
        }
    }

    // out[b][ch][h][w], ch = p*8 + t
    float* __restrict__ ob = out + (b * OUT_C + p * 8) * (H_ * W_) + h * W_ + w;
#pragma unroll
    for (int t = 0; t < 8; ++t)
        ob[t * (H_ * W_)] = acc[t];
}

// ---------------- launch ----------------
extern "C" void kernel_launch(void* const* d_in, const int* in_sizes, int n_in,
                              void* d_out, int out_size) {
    const float* x   = (const float*)d_in[0];
    const float* wgt = (const float*)d_in[1];
    const float* mos = (const float*)d_in[2];
    float* out = (float*)d_out;

    prepad_kernel<<<(PAD_TOTAL + 255) / 256, 256>>>(x);
    morr_kernel<<<(NPIX / 32) * 2, 128>>>(wgt, mos, out);
}

// round 4
// speedup vs baseline: 1.1366x; 1.1366x over previous
#include <cuda_runtime.h>

// ---------------- problem constants ----------------
#define B_      8
#define IN_C    32
#define OUT_C   64
#define H_      64
#define W_      64
#define QDIM    36
#define PDIM    8
#define KB      8
#define NPIX    (B_*H_*W_)          // 32768
#define NQP     (QDIM/2)            // 18 q-pairs
#define WSTR    12                  // floats per (q,p) weight spectrum

#define HP      66
#define CHW     (HP*HP)             // 4356
#define PAD_TOTAL (B_*IN_C*CHW)

#define MRR_A   0.987
#define MRR_R   0.99

typedef unsigned long long u64;

__device__ float g_xpad[PAD_TOTAL];
__device__ float g_wfft[QDIM * PDIM * WSTR];

// ---------------- kernel 1: zero-padded x^2 ----------------
__global__ void prepad_kernel(const float* __restrict__ x) {
    int idx = blockIdx.x * blockDim.x + threadIdx.x;
    if (idx >= PAD_TOTAL) return;
    int wp = idx % HP;
    int t  = idx / HP;
    int hp = t % HP;
    int bc = t / HP;
    float v = 0.0f;
    if (hp >= 1 && hp <= H_ && wp >= 1 && wp <= W_) {
        float xv = x[(bc * H_ + (hp - 1)) * W_ + (wp - 1)];
        v = xv * xv;
    }
    g_xpad[idx] = v;
}

// ---------------- kernel 1b: weight spectra (8-pt real FFT of |w|) -------
// layout per (q,p): [W0, W4, W1r, W1i, -W1i, W2r, W2i, -W2i, W3r, W3i, -W3i, 0]
// scales folded: bins 0,4 -> 1/8 ; bins 1..3 -> 1/4 (the 2*Re factor / 8)
__global__ void wfft_kernel(const float* __restrict__ wgt) {
    int i = threadIdx.x;
    if (i >= QDIM * PDIM) return;
    int q = i / PDIM, p = i % PDIM;
    float x[8];
#pragma unroll
    for (int s = 0; s < 8; ++s) x[s] = fabsf(wgt[p * (QDIM * KB) + q * KB + s]);
    float s0 = x[0] + x[4], s1 = x[0] - x[4], s2 = x[2] + x[6], s3 = x[2] - x[6];
    float t0 = x[1] + x[5], t1 = x[1] - x[5], t2 = x[3] + x[7], t3 = x[3] - x[7];
    float E0 = s0 + s2, O0 = t0 + t2;
    const float Cc = 0.70710678118654752f;
    float u = Cc * (t1 - t3), v = Cc * (t1 + t3);
    float W0  = (E0 + O0) * 0.125f;
    float W4  = (E0 - O0) * 0.125f;
    float W1r = (s1 + u) * 0.25f, W1i = (-s3 - v) * 0.25f;
    float W2r = (s0 - s2) * 0.25f, W2i = (t2 - t0) * 0.25f;
    float W3r = (s1 - u) * 0.25f, W3i = (s3 - v) * 0.25f;
    float* o = g_wfft + (q * PDIM + p) * WSTR;
    o[0] = W0;  o[1] = W4;
    o[2] = W1r; o[3] = W1i; o[4]  = -W1i;
    o[5] = W2r; o[6] = W2i; o[7]  = -W2i;
    o[8] = W3r; o[9] = W3i; o[10] = -W3i;
    o[11] = 0.0f;
}

// ---------------- packed f32x2 helpers ----------------
__device__ __forceinline__ u64 pack2(float a, float b) {
    u64 r; asm("mov.b64 %0, {%1, %2};" : "=l"(r) : "f"(a), "f"(b)); return r;
}
__device__ __forceinline__ void unpack2(u64 v, float& a, float& b) {
    asm("mov.b64 {%0, %1}, %2;" : "=f"(a), "=f"(b) : "l"(v));
}
__device__ __forceinline__ u64 add2(u64 a, u64 b) {
    u64 r; asm("add.rn.f32x2 %0, %1, %2;" : "=l"(r) : "l"(a), "l"(b)); return r;
}
__device__ __forceinline__ u64 sub2(u64 a, u64 b) {
    u64 r; asm("sub.rn.f32x2 %0, %1, %2;" : "=l"(r) : "l"(a), "l"(b)); return r;
}
__device__ __forceinline__ u64 mul2(u64 a, u64 b) {
    u64 r; asm("mul.rn.f32x2 %0, %1, %2;" : "=l"(r) : "l"(a), "l"(b)); return r;
}
__device__ __forceinline__ u64 fma2(u64 a, u64 b, u64 c) {
    u64 r; asm("fma.rn.f32x2 %0, %1, %2, %3;" : "=l"(r) : "l"(a), "l"(b), "l"(c)); return r;
}

// ---------------- kernel 2: main compute ----------------
// grid 1024, block 128. warp -> psplit (2 p's per thread), lane -> pixel.
__global__ __launch_bounds__(128, 6) void morr_kernel(const float* __restrict__ mos,
                                                      float* __restrict__ out) {
    // packed weight spectra across q-pair: wpk[(qp*PDIM+p)*WSTR + j] = {q0, q1}
    __shared__ u64   wpk[NQP * PDIM * WSTR];  // 13824 B
    __shared__ int   poff[QDIM * KB];
    __shared__ float scl[QDIM];

    const int tid = threadIdx.x;

    for (int d = tid; d < NQP * PDIM * WSTR; d += 128) {
        int qp = d / (PDIM * WSTR);
        int r  = d % (PDIM * WSTR);
        int p  = r / WSTR;
        int j  = r % WSTR;
        float w0 = g_wfft[((2 * qp)     * PDIM + p) * WSTR + j];
        float w1 = g_wfft[((2 * qp + 1) * PDIM + p) * WSTR + j];
        wpk[d] = pack2(w0, w1);
    }
    for (int i = tid; i < QDIM * KB; i += 128) {
        int c = i / 9, r = i % 9;
        poff[i] = c * CHW + (r / 3) * HP + (r % 3);
    }
    if (tid < QDIM) {
        const float D = (float)((1.0 - MRR_A * MRR_A) * (1.0 - MRR_R * MRR_R));
        float sv = (tid < QDIM / 2) ? mos[tid] : -mos[tid - QDIM / 2];
        scl[tid] = -D * sv;
    }
    __syncthreads();

    const int psplit = tid >> 5;
    const int lane   = tid & 31;
    const int n = blockIdx.x * 32 + lane;
    const int b = n >> 12;
    const int h = (n >> 6) & 63;
    const int w = n & 63;

    const float* __restrict__ xb = g_xpad + b * (IN_C * CHW) + h * HP + w;

    float acc[2][8];
#pragma unroll
    for (int pl = 0; pl < 2; ++pl)
#pragma unroll
        for (int t = 0; t < 8; ++t) acc[pl][t] = 0.0f;

    const float C2   = (float)(1.0 + (MRR_A * MRR_R) * (MRR_A * MRR_R));
    const float N2AR = (float)(-2.0 * MRR_A * MRR_R);
    const float Cc   = 0.70710678118654752f;
    const u64 CC2  = pack2(Cc, Cc);
    const u64 CCN2 = pack2(-Cc, -Cc);

    for (int qp = 0; qp < NQP; ++qp) {
        const float a0 = scl[2 * qp];
        const float a1 = scl[2 * qp + 1];

        // gather both q's inputs, packed across the pair
        u64 xs[8];
#pragma unroll
        for (int s = 0; s < 8; ++s) {
            float x0 = xb[poff[qp * 16 + s]];
            float x1 = xb[poff[qp * 16 + 8 + s]];
            xs[s] = pack2(x0, x1);
        }

        // forward 8-pt real FFT (packed) — shared across both p's
        u64 s0 = add2(xs[0], xs[4]), s1 = sub2(xs[0], xs[4]);
        u64 s2 = add2(xs[2], xs[6]), s3 = sub2(xs[2], xs[6]);
        u64 t0 = add2(xs[1], xs[5]), t1 = sub2(xs[1], xs[5]);
        u64 t2 = add2(xs[3], xs[7]), t3 = sub2(xs[3], xs[7]);
        u64 E0 = add2(s0, s2), O0 = add2(t0, t2);
        u64 X0  = add2(E0, O0);
        u64 X4  = sub2(E0, O0);
        u64 X2r = sub2(s0, s2);
        u64 X2i = sub2(t2, t0);
        u64 um  = sub2(t1, t3), vp = add2(t1, t3);
        u64 u_  = mul2(CC2, um);
        u64 vn  = mul2(CCN2, vp);          // = -C*(t1+t3)
        u64 X1r = add2(s1, u_);
        u64 X1i = sub2(vn, s3);            // = -s3 - v
        u64 X3r = sub2(s1, u_);
        u64 X3i = add2(s3, vn);            // = s3 - v

#pragma unroll
        for (int pl = 0; pl < 2; ++pl) {
            const int p = psplit * 2 + pl;
            const u64* __restrict__ wq = &wpk[(qp * PDIM + p) * WSTR];

            // pointwise spectral product (scales + minus-signs pre-folded)
            u64 P0  = mul2(X0, wq[0]);
            u64 P4  = mul2(X4, wq[1]);
            u64 P1r = fma2(X1i, wq[4],  mul2(X1r, wq[2]));
            u64 P1i = fma2(X1r, wq[3],  mul2(X1i, wq[2]));
            u64 P2r = fma2(X2i, wq[7],  mul2(X2r, wq[5]));
            u64 P2i = fma2(X2r, wq[6],  mul2(X2i, wq[5]));
            u64 P3r = fma2(X3i, wq[10], mul2(X3r, wq[8]));
            u64 P3i = fma2(X3r, wq[9],  mul2(X3i, wq[8]));

            // inverse 8-pt real FFT (packed) -> phases y[0..7]
            u64 A0 = add2(P0, P4), A1 = sub2(P0, P4);
            u64 e0 = add2(A0, P2r), e2 = sub2(A0, P2r);
            u64 e1 = sub2(A1, P2i), e3 = add2(A1, P2i);
            u64 o0 = add2(P1r, P3r);
            u64 o2 = sub2(P3i, P1i);
            u64 u2 = sub2(P1r, P3r), v2 = add2(P1i, P3i);
            u64 o1 = mul2(CC2,  sub2(u2, v2));
            u64 o3 = mul2(CCN2, add2(u2, v2));
            u64 y[8];
            y[0] = add2(e0, o0); y[4] = sub2(e0, o0);
            y[1] = add2(e1, o1); y[5] = sub2(e1, o1);
            y[2] = add2(e2, o2); y[6] = sub2(e2, o2);
            y[3] = add2(e3, o3); y[7] = sub2(e3, o3);

#pragma unroll
            for (int t = 0; t < 8; ++t) {
                float ph0, ph1;
                unpack2(y[t], ph0, ph1);
                float c0 = __cosf(ph0);
                float c1 = __cosf(ph1);
                float e0s = fmaf(c0, N2AR, C2);
                float e1s = fmaf(c1, N2AR, C2);
                // a0/e0 + a1/e1 = (a0*e1 + a1*e0)/(e0*e1): one RCP per q-pair
                float num = fmaf(a1, e0s, a0 * e1s);
                float den = e0s * e1s;
                float r;
                asm("rcp.approx.f32 %0, %1;" : "=f"(r) : "f"(den));
                acc[pl][t] = fmaf(num, r, acc[pl][t]);
            }
        }
    }

    float* __restrict__ ob = out + (b * OUT_C + psplit * 16) * (H_ * W_) + h * W_ + w;
#pragma unroll
    for (int pl = 0; pl < 2; ++pl)
#pragma unroll
        for (int t = 0; t < 8; ++t)
            ob[(pl * 8 + t) * (H_ * W_)] = acc[pl][t];
}

// ---------------- launch ----------------
extern "C" void kernel_launch(void* const* d_in, const int* in_sizes, int n_in,
                              void* d_out, int out_size) {
    const float* x   = (const float*)d_in[0];
    const float* wgt = (const float*)d_in[1];
    const float* mos = (const float*)d_in[2];
    float* out = (float*)d_out;

    prepad_kernel<<<(PAD_TOTAL + 255) / 256, 256>>>(x);
    wfft_kernel<<<1, 512>>>(wgt);
    morr_kernel<<<NPIX / 32, 128>>>(mos, out);
}

// round 6
// speedup vs baseline: 1.2782x; 1.1245x over previous
#include <cuda_runtime.h>

// ---------------- problem constants ----------------
#define B_      8
#define IN_C    32
#define OUT_C   64
#define H_      64
#define W_      64
#define QDIM    36
#define PDIM    8
#define KB      8
#define NPIX    (B_*H_*W_)          // 32768
#define NQP     (QDIM/2)            // 18 q-pairs
#define WSTR    12                  // u64 entries per (qp,p) packed spectrum

#define HP      66
#define CHW     (HP*HP)             // 4356
#define PAD_TOTAL (B_*IN_C*CHW)     // 1,115,136
#define PAD_Q   (PAD_TOTAL/4)       // 278,784

#define MRR_A   0.987
#define MRR_R   0.99

typedef unsigned long long u64;

__device__ float g_xpad[PAD_TOTAL];

// ---------------- kernel 1: zero-padded x^2, 4-way ILP ----------------
__global__ void prepad_kernel(const float* __restrict__ x) {
    int i0 = blockIdx.x * blockDim.x + threadIdx.x;   // 0 .. PAD_Q-1 exactly
    float v[4];
#pragma unroll
    for (int j = 0; j < 4; ++j) {
        int idx = i0 + j * PAD_Q;
        int wp = idx % HP;
        int t  = idx / HP;
        int hp = t % HP;
        int bc = t / HP;
        v[j] = 0.0f;
        if (hp >= 1 && hp <= H_ && wp >= 1 && wp <= W_) {
            float xv = __ldg(&x[(bc * H_ + (hp - 1)) * W_ + (wp - 1)]);
            v[j] = xv * xv;
        }
    }
#pragma unroll
    for (int j = 0; j < 4; ++j)
        g_xpad[i0 + j * PAD_Q] = v[j];
}

// ---------------- packed f32x2 helpers ----------------
__device__ __forceinline__ u64 pack2(float a, float b) {
    u64 r; asm("mov.b64 %0, {%1, %2};" : "=l"(r) : "f"(a), "f"(b)); return r;
}
__device__ __forceinline__ void unpack2(u64 v, float& a, float& b) {
    asm("mov.b64 {%0, %1}, %2;" : "=f"(a), "=f"(b) : "l"(v));
}
__device__ __forceinline__ u64 add2(u64 a, u64 b) {
    u64 r; asm("add.rn.f32x2 %0, %1, %2;" : "=l"(r) : "l"(a), "l"(b)); return r;
}
__device__ __forceinline__ u64 sub2(u64 a, u64 b) {
    u64 r; asm("sub.rn.f32x2 %0, %1, %2;" : "=l"(r) : "l"(a), "l"(b)); return r;
}
__device__ __forceinline__ u64 mul2(u64 a, u64 b) {
    u64 r; asm("mul.rn.f32x2 %0, %1, %2;" : "=l"(r) : "l"(a), "l"(b)); return r;
}
__device__ __forceinline__ u64 fma2(u64 a, u64 b, u64 c) {
    u64 r; asm("fma.rn.f32x2 %0, %1, %2, %3;" : "=l"(r) : "l"(a), "l"(b), "l"(c)); return r;
}

// 8-pt real FFT of |w| row, scales folded (bins 0,4 -> 1/8; bins 1-3 -> 1/4)
__device__ __forceinline__ void wspec(const float* __restrict__ wrow, float o[12]) {
    float x[8];
#pragma unroll
    for (int s = 0; s < 8; ++s) x[s] = fabsf(wrow[s]);
    float s0 = x[0] + x[4], s1 = x[0] - x[4], s2 = x[2] + x[6], s3 = x[2] - x[6];
    float t0 = x[1] + x[5], t1 = x[1] - x[5], t2 = x[3] + x[7], t3 = x[3] - x[7];
    float E0 = s0 + s2, O0 = t0 + t2;
    const float Cc = 0.70710678118654752f;
    float u = Cc * (t1 - t3), v = Cc * (t1 + t3);
    o[0]  = (E0 + O0) * 0.125f;
    o[1]  = (E0 - O0) * 0.125f;
    o[2]  = (s1 + u) * 0.25f;  o[3] = (-s3 - v) * 0.25f;  o[4]  = -o[3];
    o[5]  = (s0 - s2) * 0.25f; o[6] = (t2 - t0) * 0.25f;  o[7]  = -o[6];
    o[8]  = (s1 - u) * 0.25f;  o[9] = (s3 - v) * 0.25f;   o[10] = -o[9];
    o[11] = 0.0f;
}

// ---------------- kernel 2: main compute (wfft fused into shared init) ----
// grid 1024, block 128. warp -> psplit (2 p's per thread), lane -> pixel.
__global__ __launch_bounds__(128, 6) void morr_kernel(const float* __restrict__ wgt,
                                                      const float* __restrict__ mos,
                                                      float* __restrict__ out) {
    __shared__ u64   wpk[NQP * PDIM * WSTR];  // packed {q0,q1} spectra, 13824 B
    __shared__ int   poff[QDIM * KB];
    __shared__ float scl[QDIM];

    const int tid = threadIdx.x;

    // fused weight-spectrum computation: 144 (qp,p) pairs, grid-strided over 128 threads
    for (int d = tid; d < NQP * PDIM; d += 128) {
        int qp = d >> 3;
        int p  = d & 7;
        float sA[12], sB[12];
        wspec(wgt + p * (QDIM * KB) + (2 * qp) * KB,     sA);
        wspec(wgt + p * (QDIM * KB) + (2 * qp + 1) * KB, sB);
        u64* o = &wpk[(qp * PDIM + p) * WSTR];
#pragma unroll
        for (int j = 0; j < 12; ++j) o[j] = pack2(sA[j], sB[j]);
    }
    for (int i = tid; i < QDIM * KB; i += 128) {
        int c = i / 9, r = i % 9;
        poff[i] = c * CHW + (r / 3) * HP + (r % 3);
    }
    if (tid < QDIM) {
        const float D = (float)((1.0 - MRR_A * MRR_A) * (1.0 - MRR_R * MRR_R));
        float sv = (tid < QDIM / 2) ? mos[tid] : -mos[tid - QDIM / 2];
        scl[tid] = -D * sv;
    }
    __syncthreads();

    const int psplit = tid >> 5;
    const int lane   = tid & 31;
    const int n = blockIdx.x * 32 + lane;
    const int b = n >> 12;
    const int h = (n >> 6) & 63;
    const int w = n & 63;

    const float* __restrict__ xb = g_xpad + b * (IN_C * CHW) + h * HP + w;

    float acc[2][8];
#pragma unroll
    for (int pl = 0; pl < 2; ++pl)
#pragma unroll
        for (int t = 0; t < 8; ++t) acc[pl][t] = 0.0f;

    const float C2   = (float)(1.0 + (MRR_A * MRR_R) * (MRR_A * MRR_R));
    const float N2AR = (float)(-2.0 * MRR_A * MRR_R);
    const u64 C22   = pack2(C2, C2);
    const u64 N2AR2 = pack2(N2AR, N2AR);
    const float Cc = 0.70710678118654752f;
    const u64 CC2  = pack2(Cc, Cc);
    const u64 CCN2 = pack2(-Cc, -Cc);

    for (int qp = 0; qp < NQP; ++qp) {
        const float a0 = scl[2 * qp];
        const float a1 = scl[2 * qp + 1];

        // gather both q's inputs, packed across the pair
        u64 xs[8];
#pragma unroll
        for (int s = 0; s < 8; ++s) {
            float x0 = xb[poff[qp * 16 + s]];
            float x1 = xb[poff[qp * 16 + 8 + s]];
            xs[s] = pack2(x0, x1);
        }

        // forward 8-pt real FFT (packed) — shared across both p's
        u64 s0 = add2(xs[0], xs[4]), s1 = sub2(xs[0], xs[4]);
        u64 s2 = add2(xs[2], xs[6]), s3 = sub2(xs[2], xs[6]);
        u64 t0 = add2(xs[1], xs[5]), t1 = sub2(xs[1], xs[5]);
        u64 t2 = add2(xs[3], xs[7]), t3 = sub2(xs[3], xs[7]);
        u64 E0 = add2(s0, s2), O0 = add2(t0, t2);
        u64 X0  = add2(E0, O0);
        u64 X4  = sub2(E0, O0);
        u64 X2r = sub2(s0, s2);
        u64 X2i = sub2(t2, t0);
        u64 um  = sub2(t1, t3), vp = add2(t1, t3);
        u64 u_  = mul2(CC2, um);
        u64 vn  = mul2(CCN2, vp);
        u64 X1r = add2(s1, u_);
        u64 X1i = sub2(vn, s3);
        u64 X3r = sub2(s1, u_);
        u64 X3i = add2(s3, vn);

#pragma unroll
        for (int pl = 0; pl < 2; ++pl) {
            const int p = psplit * 2 + pl;
            const u64* __restrict__ wq = &wpk[(qp * PDIM + p) * WSTR];

            // pointwise spectral product (scales + minus-signs pre-folded)
            u64 P0  = mul2(X0, wq[0]);
            u64 P4  = mul2(X4, wq[1]);
            u64 P1r = fma2(X1i, wq[4],  mul2(X1r, wq[2]));
            u64 P1i = fma2(X1r, wq[3],  mul2(X1i, wq[2]));
            u64 P2r = fma2(X2i, wq[7],  mul2(X2r, wq[5]));
            u64 P2i = fma2(X2r, wq[6],  mul2(X2i, wq[5]));
            u64 P3r = fma2(X3i, wq[10], mul2(X3r, wq[8]));
            u64 P3i = fma2(X3r, wq[9],  mul2(X3i, wq[8]));

            // inverse 8-pt real FFT (packed) -> phases y[0..7]
            u64 A0 = add2(P0, P4), A1 = sub2(P0, P4);
            u64 e0 = add2(A0, P2r), e2 = sub2(A0, P2r);
            u64 e1 = sub2(A1, P2i), e3 = add2(A1, P2i);
            u64 o0 = add2(P1r, P3r);
            u64 o2 = sub2(P3i, P1i);
            u64 u2 = sub2(P1r, P3r), v2 = add2(P1i, P3i);
            u64 o1 = mul2(CC2,  sub2(u2, v2));
            u64 o3 = mul2(CCN2, add2(u2, v2));
            u64 y[8];
            y[0] = add2(e0, o0); y[4] = sub2(e0, o0);
            y[1] = add2(e1, o1); y[5] = sub2(e1, o1);
            y[2] = add2(e2, o2); y[6] = sub2(e2, o2);
            y[3] = add2(e3, o3); y[7] = sub2(e3, o3);

#pragma unroll
            for (int t = 0; t < 8; ++t) {
                float ph0, ph1;
                unpack2(y[t], ph0, ph1);
                float c0 = __cosf(ph0);
                float c1 = __cosf(ph1);
                // packed e = C2 - 2AR*cos
                u64 epk = fma2(pack2(c0, c1), N2AR2, C22);
                float e0s, e1s;
                unpack2(epk, e0s, e1s);
                // a0/e0 + a1/e1 = (a0*e1 + a1*e0)/(e0*e1): one RCP per q-pair
                float num = fmaf(a1, e0s, a0 * e1s);
                float den = e0s * e1s;
                float r;
                asm("rcp.approx.f32 %0, %1;" : "=f"(r) : "f"(den));
                acc[pl][t] = fmaf(num, r, acc[pl][t]);
            }
        }
    }

    float* __restrict__ ob = out + (b * OUT_C + psplit * 16) * (H_ * W_) + h * W_ + w;
#pragma unroll
    for (int pl = 0; pl < 2; ++pl)
#pragma unroll
        for (int t = 0; t < 8; ++t)
            ob[(pl * 8 + t) * (H_ * W_)] = acc[pl][t];
}

// ---------------- launch ----------------
extern "C" void kernel_launch(void* const* d_in, const int* in_sizes, int n_in,
                              void* d_out, int out_size) {
    const float* x   = (const float*)d_in[0];
    const float* wgt = (const float*)d_in[1];
    const float* mos = (const float*)d_in[2];
    float* out = (float*)d_out;

    prepad_kernel<<<PAD_Q / 256, 256>>>(x);
    morr_kernel<<<NPIX / 32, 128>>>(wgt, mos, out);
}